// round 11
// baseline (speedup 1.0000x reference)
#include <cuda_runtime.h>
#include <cuda_pipeline.h>
#include <cuda_bf16.h>

// Problem constants
#define NB   4096
#define NH   4096
#define HCD  16384
#define MIX  24

// Pass-1 tiling
#define BM     16     // batch rows per block (= MMA M)
#define CH     64     // h per slab
#define HR     512    // h range per block  (grid 256 x 8 = 2048 tiles)
#define NSLAB  8      // HR / CH
#define NSPL   8      // h-split partial count (NH/HR)

// d_out layout: residual_cur | post_mix | comb_mix | layer_input
#define RES_OFF   0ULL
#define POST_OFF  67108864ULL
#define COMB_OFF  (POST_OFF + 16384ULL)
#define LAYER_OFF (COMB_OFF + 65536ULL)

// dynamic smem (bytes): fnH[2][24][264] | fnL[2] | outH[16][264] | outL  (bf16)
#define FNH_STAGE  12672              // 24*264*2
#define OUT_STAGE  8448               // 16*264*2
#define FNH_OFF    0
#define FNL_OFF    25344
#define OUTH_OFF   50688
#define OUTL_OFF   59136
#define SMEM_DYN   67584

typedef unsigned long long u64;

// Scratch (no allocations allowed -> __device__ globals)
__device__ unsigned g_fnhi2[24 * 16384 / 2];   // bf16x2-packed fn hi
__device__ unsigned g_fnlo2[24 * 16384 / 2];   // bf16x2-packed fn lo
__device__ float g_lp[NSPL][NB][MIX];
__device__ float g_ssq[NSPL][NB];
__device__ float g_hpre[NB][4];

__device__ __forceinline__ unsigned bf2pack(float e0, float e1) {
    __nv_bfloat162 v = __floats2bfloat162_rn(e0, e1);  // .x=e0 (lower), .y=e1
    unsigned r; memcpy(&r, &v, 4); return r;
}
__device__ __forceinline__ float bf_lo_f(unsigned u) { return __uint_as_float(u << 16); }
__device__ __forceinline__ float bf_hi_f(unsigned u) { return __uint_as_float(u & 0xffff0000u); }

__device__ __forceinline__ void ldsm_x4(unsigned addr, unsigned& r0, unsigned& r1,
                                        unsigned& r2, unsigned& r3) {
    asm volatile("ldmatrix.sync.aligned.m8n8.x4.shared.b16 {%0,%1,%2,%3}, [%4];"
                 : "=r"(r0), "=r"(r1), "=r"(r2), "=r"(r3) : "r"(addr));
}
__device__ __forceinline__ void ldsm_x2(unsigned addr, unsigned& r0, unsigned& r1) {
    asm volatile("ldmatrix.sync.aligned.m8n8.x2.shared.b16 {%0,%1}, [%2];"
                 : "=r"(r0), "=r"(r1) : "r"(addr));
}
__device__ __forceinline__ void mma_bf16(float* d, const unsigned* a, unsigned b0, unsigned b1) {
    asm volatile(
        "mma.sync.aligned.m16n8k16.row.col.f32.bf16.bf16.f32 "
        "{%0,%1,%2,%3}, {%4,%5,%6,%7}, {%8,%9}, {%0,%1,%2,%3};"
        : "+f"(d[0]), "+f"(d[1]), "+f"(d[2]), "+f"(d[3])
        : "r"(a[0]), "r"(a[1]), "r"(a[2]), "r"(a[3]), "r"(b0), "r"(b1));
}

// ---------------------------------------------------------------------------
// Pre-pass: split fn (fp32) into bf16 hi/lo device arrays. 24*16384 elements.
// ---------------------------------------------------------------------------
__global__ __launch_bounds__(256) void k_split_fn(const float* __restrict__ fn)
{
    const int t = blockIdx.x * 256 + threadIdx.x;     // 98304 threads, 4 el each
    const float4 v = *(const float4*)(fn + (size_t)t * 4);
    unsigned h01 = bf2pack(v.x, v.y), h23 = bf2pack(v.z, v.w);
    unsigned l01 = bf2pack(v.x - bf_lo_f(h01), v.y - bf_hi_f(h01));
    unsigned l23 = bf2pack(v.z - bf_lo_f(h23), v.w - bf_hi_f(h23));
    g_fnhi2[t * 2] = h01; g_fnhi2[t * 2 + 1] = h23;
    g_fnlo2[t * 2] = l01; g_fnlo2[t * 2 + 1] = l23;
}

// ---------------------------------------------------------------------------
// Pass 1: residual_cur = comb@residual_prev + post*x ; write it; fused sumsq
// and 24 raw dots vs fn — dots via bf16 split-precision HMMA (m16n8k16).
//   - raw x/residual: distance-1 register prefetch
//   - fn slabs: cp.async DOUBLE buffer; outS SINGLE buffer (2 barriers/slab)
//   - smem 67.6KB -> 3 blocks/SM; HR=512 -> grid 2048 -> 92% wave utilization
// Grid: (NB/BM, NH/HR) = (256, 8), 256 threads (8 warps).
// ---------------------------------------------------------------------------
__global__ __launch_bounds__(256, 3) void k_pass1(
    const float* __restrict__ x, const float* __restrict__ rprev,
    const float* __restrict__ postp, const float* __restrict__ combp,
    float* __restrict__ out)
{
    extern __shared__ char smc[];
    float* red = (float*)(smc + OUTH_OFF);   // overlay [384][8], epilogue only
    const unsigned smu = (unsigned)__cvta_generic_to_shared(smc);

    __shared__ float comb_s[BM][16];
    __shared__ float post_s[BM][4];

    const int tid  = threadIdx.x;
    const int lane = tid & 31;
    const int w    = tid >> 5;               // warp 0..7
    const int b0   = blockIdx.x * BM;
    const int h0   = blockIdx.y * HR;

    for (int i = tid; i < BM * 16; i += 256)
        comb_s[i >> 4][i & 15] = combp[(size_t)(b0 + (i >> 4)) * 16 + (i & 15)];
    if (tid < BM * 4)
        post_s[tid >> 2][tid & 3] = postp[(size_t)b0 * 4 + tid];

    // compute-phase mapping: one float4-of-h per thread, fixed row
    const int crow = tid >> 4;               // 0..15
    const int ch4  = (tid & 15) << 2;        // 0..60

    const int bg = b0 + crow;
    const float* xrow = x + (size_t)bg * NH;
    const float* rrow = rprev + (size_t)bg * 4 * NH;
    float* orow = out + RES_OFF + (size_t)bg * 4 * NH;

    // prologue: cp.async fn slab 0 (stage 0)
    {
        #pragma unroll
        for (int k = 0; k < 3; k++) {
            int q = tid + k * 256, m = q >> 5, col = (q & 31) * 8;
            size_t so = ((size_t)m * HCD + (col >> 6) * NH + h0 + (col & 63)) * 2;
            unsigned dst = m * 528 + col * 2;
            __pipeline_memcpy_async(smc + FNH_OFF + dst, (const char*)g_fnhi2 + so, 16);
            __pipeline_memcpy_async(smc + FNL_OFF + dst, (const char*)g_fnlo2 + so, 16);
        }
        __pipeline_commit();
    }

    float4 xv_p = __ldcs((const float4*)(xrow + h0 + ch4));
    float4 rv_p[4];
    #pragma unroll
    for (int j = 0; j < 4; j++)
        rv_p[j] = __ldcs((const float4*)(rrow + (size_t)j * NH + h0 + ch4));

    float D[3][4];
    #pragma unroll
    for (int j = 0; j < 3; j++)
        #pragma unroll
        for (int r = 0; r < 4; r++) D[j][r] = 0.f;
    float ssq = 0.f;

    // ldmatrix lane address components (byte offsets within a stage)
    const unsigned aRow = (lane & 15) * 528 + ((lane >> 4) << 4);      // + c*32
    const unsigned bRow = (lane & 7) * 528 + (((lane >> 3) & 1) << 4); // + j*8*528 + c*32

    __syncthreads();   // comb_s/post_s visible

    for (int s = 0; s < NSLAB; s++) {
        const int st = s & 1;
        const int hh0 = h0 + s * CH;

        // ---- A phase: residual compute; fp32 to gmem; bf16 hi/lo to outS
        {
            const int hg = hh0 + ch4;
            const unsigned ob = crow * 528 + ch4 * 2;   // + n*128
            #pragma unroll
            for (int n = 0; n < 4; n++) {
                const float ppn = post_s[crow][n];
                float4 o;
                o.x = ppn * xv_p.x; o.y = ppn * xv_p.y;
                o.z = ppn * xv_p.z; o.w = ppn * xv_p.w;
                #pragma unroll
                for (int j = 0; j < 4; j++) {
                    const float cbv = comb_s[crow][n * 4 + j];
                    o.x += cbv * rv_p[j].x; o.y += cbv * rv_p[j].y;
                    o.z += cbv * rv_p[j].z; o.w += cbv * rv_p[j].w;
                }
                __stcs((float4*)(orow + (size_t)n * NH + hg), o);
                ssq += o.x * o.x + o.y * o.y + o.z * o.z + o.w * o.w;

                unsigned h01 = bf2pack(o.x, o.y), h23 = bf2pack(o.z, o.w);
                unsigned l01 = bf2pack(o.x - bf_lo_f(h01), o.y - bf_hi_f(h01));
                unsigned l23 = bf2pack(o.z - bf_lo_f(h23), o.w - bf_hi_f(h23));
                *(u64*)(smc + OUTH_OFF + ob + n * 128) = (u64)h01 | ((u64)h23 << 32);
                *(u64*)(smc + OUTL_OFF + ob + n * 128) = (u64)l01 | ((u64)l23 << 32);
            }
        }

        // distance-1 register prefetch of raw operands for slab s+1
        if (s + 1 < NSLAB) {
            const int hg1 = hh0 + CH + ch4;
            xv_p = __ldcs((const float4*)(xrow + hg1));
            #pragma unroll
            for (int j = 0; j < 4; j++)
                rv_p[j] = __ldcs((const float4*)(rrow + (size_t)j * NH + hg1));
        }

        __pipeline_wait_prior(0);
        __syncthreads();   // bar1: outS(s) + fnS[st](s) visible to all warps

        // prefetch fn slab s+1 into the other fn stage
        if (s + 1 < NSLAB) {
            const int hb1 = (s + 1) * CH;
            #pragma unroll
            for (int k = 0; k < 3; k++) {
                int q = tid + k * 256, m = q >> 5, col = (q & 31) * 8;
                size_t so = ((size_t)m * HCD + (col >> 6) * NH + h0 + hb1 + (col & 63)) * 2;
                unsigned dst = (st ^ 1) * FNH_STAGE + m * 528 + col * 2;
                __pipeline_memcpy_async(smc + FNH_OFF + dst, (const char*)g_fnhi2 + so, 16);
                __pipeline_memcpy_async(smc + FNL_OFF + dst, (const char*)g_fnlo2 + so, 16);
            }
            __pipeline_commit();
        }

        // ---- GEMM via HMMA: warp w handles k-chunks {w, w+8} (16 k each)
        #pragma unroll
        for (int cc = 0; cc < 2; cc++) {
            const int c = w + cc * 8;
            unsigned ah[4], al[4];
            ldsm_x4(smu + OUTH_OFF + aRow + c * 32, ah[0], ah[1], ah[2], ah[3]);
            ldsm_x4(smu + OUTL_OFF + aRow + c * 32, al[0], al[1], al[2], al[3]);
            #pragma unroll
            for (int j = 0; j < 3; j++) {
                unsigned bh0, bh1, bl0, bl1;
                const unsigned bo = st * FNH_STAGE + j * 8 * 528 + bRow + c * 32;
                ldsm_x2(smu + FNH_OFF + bo, bh0, bh1);
                ldsm_x2(smu + FNL_OFF + bo, bl0, bl1);
                mma_bf16(D[j], ah, bh0, bh1);
                mma_bf16(D[j], ah, bl0, bl1);
                mma_bf16(D[j], al, bh0, bh1);
            }
        }
        __syncthreads();   // bar2: GEMM(s) done -> outS free for A(s+1)
    }

    // --- logits reduction across 8 warps via red overlay (outS region, free now)
    {
        const int row = lane >> 2, col2 = (lane & 3) * 2;
        #pragma unroll
        for (int j = 0; j < 3; j++) {
            const int m = j * 8 + col2;
            red[((row)     * 24 + m)     * 8 + w] = D[j][0];
            red[((row)     * 24 + m + 1) * 8 + w] = D[j][1];
            red[((row + 8) * 24 + m)     * 8 + w] = D[j][2];
            red[((row + 8) * 24 + m + 1) * 8 + w] = D[j][3];
        }
    }
    __syncthreads();
    for (int o = tid; o < 384; o += 256) {
        const int row = o / 24, m = o % 24;
        float v = 0.f;
        #pragma unroll
        for (int ww = 0; ww < 8; ww++) v += red[(row * 24 + m) * 8 + ww];
        g_lp[blockIdx.y][b0 + row][m] = v;
    }

    // --- sumsq: 16 lanes share crow
    float v = ssq;
    v += __shfl_xor_sync(0xffffffffu, v, 1);
    v += __shfl_xor_sync(0xffffffffu, v, 2);
    v += __shfl_xor_sync(0xffffffffu, v, 4);
    v += __shfl_xor_sync(0xffffffffu, v, 8);
    if ((tid & 15) == 0) g_ssq[blockIdx.y][bg] = v;
}

// ---------------------------------------------------------------------------
// Pass 2: per-row finalize — rms, softmax, sigmoid, Sinkhorn. One thread / row.
// ---------------------------------------------------------------------------
__global__ __launch_bounds__(256) void k_mid(
    const float* __restrict__ base, const float* __restrict__ scale,
    float* __restrict__ out)
{
    const int b = blockIdx.x * 256 + threadIdx.x;
    if (b >= NB) return;

    float lg[MIX];
    #pragma unroll
    for (int m = 0; m < MIX; m++) {
        float v = 0.f;
        #pragma unroll
        for (int p = 0; p < NSPL; p++) v += g_lp[p][b][m];
        lg[m] = v;
    }
    float ss = 0.f;
    #pragma unroll
    for (int p = 0; p < NSPL; p++) ss += g_ssq[p][b];
    const float inv = rsqrtf(ss * (1.0f / HCD) + 1e-6f);

    const float s0 = scale[0], s1 = scale[1], s2 = scale[2];

    float pre[4], mx = -1e30f;
    #pragma unroll
    for (int i = 0; i < 4; i++) {
        pre[i] = lg[i] * inv * s0 + base[i];
        mx = fmaxf(mx, pre[i]);
    }
    float e[4], den = 0.f;
    #pragma unroll
    for (int i = 0; i < 4; i++) { e[i] = expf(pre[i] - mx); den += e[i]; }
    const float rden = 1.f / den;
    #pragma unroll
    for (int i = 0; i < 4; i++) g_hpre[b][i] = e[i] * rden;

    #pragma unroll
    for (int i = 0; i < 4; i++) {
        const float p = lg[4 + i] * inv * s1 + base[4 + i];
        out[POST_OFF + (size_t)b * 4 + i] = 1.f / (1.f + expf(-p));
    }

    float M[4][4];
    #pragma unroll
    for (int i = 0; i < 4; i++)
        #pragma unroll
        for (int j = 0; j < 4; j++)
            M[i][j] = expf(lg[8 + i * 4 + j] * inv * s2 + base[8 + i * 4 + j]);
    #pragma unroll
    for (int it = 0; it < 10; it++) {
        #pragma unroll
        for (int i = 0; i < 4; i++) {
            const float r = 1.f / (M[i][0] + M[i][1] + M[i][2] + M[i][3] + 1e-6f);
            #pragma unroll
            for (int j = 0; j < 4; j++) M[i][j] *= r;
        }
        #pragma unroll
        for (int j = 0; j < 4; j++) {
            const float c = 1.f / (M[0][j] + M[1][j] + M[2][j] + M[3][j] + 1e-6f);
            #pragma unroll
            for (int i = 0; i < 4; i++) M[i][j] *= c;
        }
    }
    #pragma unroll
    for (int i = 0; i < 4; i++)
        #pragma unroll
        for (int j = 0; j < 4; j++)
            out[COMB_OFF + (size_t)b * 16 + i * 4 + j] = M[i][j];
}

// ---------------------------------------------------------------------------
// Pass 3: layer_input[b,h] = sum_n h_pre[b,n] * residual_cur[b,n,h]
// ---------------------------------------------------------------------------
__global__ __launch_bounds__(256) void k_layer(float* __restrict__ out)
{
    const int b = blockIdx.x;
    const int h = (blockIdx.y * 256 + threadIdx.x) << 2;
    const float h0 = g_hpre[b][0], h1 = g_hpre[b][1];
    const float h2 = g_hpre[b][2], h3 = g_hpre[b][3];
    const float* rp = out + RES_OFF + (size_t)b * 4 * NH;
    const float4 a0 = __ldcs((const float4*)(rp + h));
    const float4 a1 = __ldcs((const float4*)(rp + NH + h));
    const float4 a2 = __ldcs((const float4*)(rp + 2 * NH + h));
    const float4 a3 = __ldcs((const float4*)(rp + 3 * NH + h));
    float4 o;
    o.x = h0 * a0.x + h1 * a1.x + h2 * a2.x + h3 * a3.x;
    o.y = h0 * a0.y + h1 * a1.y + h2 * a2.y + h3 * a3.y;
    o.z = h0 * a0.z + h1 * a1.z + h2 * a2.z + h3 * a3.z;
    o.w = h0 * a0.w + h1 * a1.w + h2 * a2.w + h3 * a3.w;
    __stcs((float4*)(out + LAYER_OFF + (size_t)b * NH + h), o);
}

extern "C" void kernel_launch(void* const* d_in, const int* in_sizes, int n_in,
                              void* d_out, int out_size)
{
    const float* x     = (const float*)d_in[0];
    const float* rprev = (const float*)d_in[1];
    const float* postp = (const float*)d_in[2];
    const float* combp = (const float*)d_in[3];
    const float* fn    = (const float*)d_in[4];
    const float* base  = (const float*)d_in[5];
    const float* scale = (const float*)d_in[6];
    float* out = (float*)d_out;

    cudaFuncSetAttribute(k_pass1, cudaFuncAttributeMaxDynamicSharedMemorySize, SMEM_DYN);
    k_split_fn<<<24 * 16384 / 1024, 256>>>(fn);
    k_pass1<<<dim3(NB / BM, NH / HR), 256, SMEM_DYN>>>(x, rprev, postp, combp, out);
    k_mid<<<NB / 256, 256>>>(base, scale, out);
    k_layer<<<dim3(NB, NH / 1024), 256>>>(out);
}

// round 12
// speedup vs baseline: 1.0413x; 1.0413x over previous
#include <cuda_runtime.h>
#include <cuda_pipeline.h>
#include <cuda_bf16.h>

// Problem constants
#define NB   4096
#define NH   4096
#define HCD  16384
#define MIX  24

// Pass-1 tiling
#define BM     16     // batch rows per tile (= MMA M)
#define CH     64     // h per slab
#define HR     1024   // h range per tile
#define NSLAB  16     // HR / CH
#define NTILES 1024   // (NB/BM) * (NH/HR)
#define NBLK   296    // persistent blocks = 2 per SM * 148

// d_out layout: residual_cur | post_mix | comb_mix | layer_input
#define RES_OFF   0ULL
#define POST_OFF  67108864ULL
#define COMB_OFF  (POST_OFF + 16384ULL)
#define LAYER_OFF (COMB_OFF + 65536ULL)

// dynamic smem (bytes): fnH[2][24][264] | fnL | outH[2][16][264] | outL   (bf16)
#define FNH_STAGE  12672              // 24*264*2
#define OUT_STAGE  8448               // 16*264*2
#define FNH_OFF    0
#define FNL_OFF    25344
#define OUTH_OFF   50688
#define OUTL_OFF   67584
#define SMEM_DYN   84480

typedef unsigned long long u64;

// Scratch (no allocations allowed -> __device__ globals)
__device__ unsigned g_fnhi2[24 * 16384 / 2];   // bf16x2-packed fn hi
__device__ unsigned g_fnlo2[24 * 16384 / 2];   // bf16x2-packed fn lo
__device__ float g_lp[4][NB][MIX];
__device__ float g_ssq[4][NB];
__device__ float g_hpre[NB][4];
__device__ unsigned g_tile;                    // work-stealing cursor

__device__ __forceinline__ unsigned bf2pack(float e0, float e1) {
    __nv_bfloat162 v = __floats2bfloat162_rn(e0, e1);  // .x=e0 (lower), .y=e1
    unsigned r; memcpy(&r, &v, 4); return r;
}
__device__ __forceinline__ float bf_lo_f(unsigned u) { return __uint_as_float(u << 16); }
__device__ __forceinline__ float bf_hi_f(unsigned u) { return __uint_as_float(u & 0xffff0000u); }

__device__ __forceinline__ void ldsm_x4(unsigned addr, unsigned& r0, unsigned& r1,
                                        unsigned& r2, unsigned& r3) {
    asm volatile("ldmatrix.sync.aligned.m8n8.x4.shared.b16 {%0,%1,%2,%3}, [%4];"
                 : "=r"(r0), "=r"(r1), "=r"(r2), "=r"(r3) : "r"(addr));
}
__device__ __forceinline__ void ldsm_x2(unsigned addr, unsigned& r0, unsigned& r1) {
    asm volatile("ldmatrix.sync.aligned.m8n8.x2.shared.b16 {%0,%1}, [%2];"
                 : "=r"(r0), "=r"(r1) : "r"(addr));
}
__device__ __forceinline__ void mma_bf16(float* d, const unsigned* a, unsigned b0, unsigned b1) {
    asm volatile(
        "mma.sync.aligned.m16n8k16.row.col.f32.bf16.bf16.f32 "
        "{%0,%1,%2,%3}, {%4,%5,%6,%7}, {%8,%9}, {%0,%1,%2,%3};"
        : "+f"(d[0]), "+f"(d[1]), "+f"(d[2]), "+f"(d[3])
        : "r"(a[0]), "r"(a[1]), "r"(a[2]), "r"(a[3]), "r"(b0), "r"(b1));
}

// ---------------------------------------------------------------------------
// Pre-pass: split fn (fp32) into bf16 hi/lo device arrays; reset tile cursor.
// ---------------------------------------------------------------------------
__global__ __launch_bounds__(256) void k_split_fn(const float* __restrict__ fn)
{
    if (blockIdx.x == 0 && threadIdx.x == 0) g_tile = 0;
    const int t = blockIdx.x * 256 + threadIdx.x;     // 98304 threads, 4 el each
    const float4 v = *(const float4*)(fn + (size_t)t * 4);
    unsigned h01 = bf2pack(v.x, v.y), h23 = bf2pack(v.z, v.w);
    unsigned l01 = bf2pack(v.x - bf_lo_f(h01), v.y - bf_hi_f(h01));
    unsigned l23 = bf2pack(v.z - bf_lo_f(h23), v.w - bf_hi_f(h23));
    g_fnhi2[t * 2] = h01; g_fnhi2[t * 2 + 1] = h23;
    g_fnlo2[t * 2] = l01; g_fnlo2[t * 2 + 1] = l23;
}

// ---------------------------------------------------------------------------
// Pass 1 (persistent): per tile — residual_cur = comb@residual_prev + post*x;
// write it; fused sumsq and 24 raw dots vs fn via bf16 split-precision HMMA.
//   - raw x/residual: distance-1 register prefetch
//   - fn slabs: cp.async double buffer; outS double buffer; 1 barrier/slab
//   - 296 persistent blocks steal tiles via atomicAdd -> no wave-tail loss
// ---------------------------------------------------------------------------
__global__ __launch_bounds__(256, 2) void k_pass1(
    const float* __restrict__ x, const float* __restrict__ rprev,
    const float* __restrict__ postp, const float* __restrict__ combp,
    float* __restrict__ out)
{
    extern __shared__ char smc[];
    float* red = (float*)(smc + OUTH_OFF);   // overlay [384][8], epilogue only
    const unsigned smu = (unsigned)__cvta_generic_to_shared(smc);

    __shared__ float comb_s[BM][16];
    __shared__ float post_s[BM][4];
    __shared__ unsigned tile_s;

    const int tid  = threadIdx.x;
    const int lane = tid & 31;
    const int w    = tid >> 5;               // warp 0..7
    const int crow = tid >> 4;               // 0..15
    const int ch4  = (tid & 15) << 2;        // 0..60

    // ldmatrix lane address components (byte offsets within a stage)
    const unsigned aRow = (lane & 15) * 528 + ((lane >> 4) << 4);      // + c*32
    const unsigned bRow = (lane & 7) * 528 + (((lane >> 3) & 1) << 4); // + j*8*528 + c*32

    for (;;) {
        // ---- steal a tile
        if (tid == 0) tile_s = atomicAdd(&g_tile, 1u);
        __syncthreads();
        const unsigned t = tile_s;
        if (t >= NTILES) break;
        const int bx = t & 255;              // 256 b-tiles
        const int by = t >> 8;               // 4 h-tiles; concurrent tiles share by
        const int b0 = bx * BM;
        const int h0 = by * HR;

        for (int i = tid; i < BM * 16; i += 256)
            comb_s[i >> 4][i & 15] = combp[(size_t)(b0 + (i >> 4)) * 16 + (i & 15)];
        if (tid < BM * 4)
            post_s[tid >> 2][tid & 3] = postp[(size_t)b0 * 4 + tid];

        const int bg = b0 + crow;
        const float* xrow = x + (size_t)bg * NH;
        const float* rrow = rprev + (size_t)bg * 4 * NH;
        float* orow = out + RES_OFF + (size_t)bg * 4 * NH;

        // prologue: cp.async fn slab 0 (stage 0)
        #pragma unroll
        for (int k = 0; k < 3; k++) {
            int q = tid + k * 256, m = q >> 5, col = (q & 31) * 8;
            size_t so = ((size_t)m * HCD + (col >> 6) * NH + h0 + (col & 63)) * 2;
            unsigned dst = m * 528 + col * 2;
            __pipeline_memcpy_async(smc + FNH_OFF + dst, (const char*)g_fnhi2 + so, 16);
            __pipeline_memcpy_async(smc + FNL_OFF + dst, (const char*)g_fnlo2 + so, 16);
        }
        __pipeline_commit();

        float4 xv_p = __ldcs((const float4*)(xrow + h0 + ch4));
        float4 rv_p[4];
        #pragma unroll
        for (int j = 0; j < 4; j++)
            rv_p[j] = __ldcs((const float4*)(rrow + (size_t)j * NH + h0 + ch4));

        float D[3][4];
        #pragma unroll
        for (int j = 0; j < 3; j++)
            #pragma unroll
            for (int r = 0; r < 4; r++) D[j][r] = 0.f;
        float ssq = 0.f;

        __syncthreads();   // comb_s/post_s visible; prior-tile epilogue fully done

        for (int s = 0; s < NSLAB; s++) {
            const int st = s & 1;
            const int hh0 = h0 + s * CH;

            // ---- A phase: residual compute; fp32 to gmem; bf16 hi/lo to outS[st]
            {
                const int hg = hh0 + ch4;
                const unsigned ob = st * OUT_STAGE + crow * 528 + ch4 * 2; // +n*128
                #pragma unroll
                for (int n = 0; n < 4; n++) {
                    const float ppn = post_s[crow][n];
                    float4 o;
                    o.x = ppn * xv_p.x; o.y = ppn * xv_p.y;
                    o.z = ppn * xv_p.z; o.w = ppn * xv_p.w;
                    #pragma unroll
                    for (int j = 0; j < 4; j++) {
                        const float cbv = comb_s[crow][n * 4 + j];
                        o.x += cbv * rv_p[j].x; o.y += cbv * rv_p[j].y;
                        o.z += cbv * rv_p[j].z; o.w += cbv * rv_p[j].w;
                    }
                    __stcs((float4*)(orow + (size_t)n * NH + hg), o);
                    ssq += o.x * o.x + o.y * o.y + o.z * o.z + o.w * o.w;

                    unsigned h01 = bf2pack(o.x, o.y), h23 = bf2pack(o.z, o.w);
                    unsigned l01 = bf2pack(o.x - bf_lo_f(h01), o.y - bf_hi_f(h01));
                    unsigned l23 = bf2pack(o.z - bf_lo_f(h23), o.w - bf_hi_f(h23));
                    *(u64*)(smc + OUTH_OFF + ob + n * 128) = (u64)h01 | ((u64)h23 << 32);
                    *(u64*)(smc + OUTL_OFF + ob + n * 128) = (u64)l01 | ((u64)l23 << 32);
                }
            }

            // distance-1 register prefetch of raw operands for slab s+1
            if (s + 1 < NSLAB) {
                const int hg1 = hh0 + CH + ch4;
                xv_p = __ldcs((const float4*)(xrow + hg1));
                #pragma unroll
                for (int j = 0; j < 4; j++)
                    rv_p[j] = __ldcs((const float4*)(rrow + (size_t)j * NH + hg1));
            }

            __pipeline_wait_prior(0);
            __syncthreads();   // fn(s)+outS[st] visible; GEMM(s-1) done everywhere

            // prefetch fn slab s+1 into the other fn stage
            if (s + 1 < NSLAB) {
                const int hb1 = (s + 1) * CH;
                #pragma unroll
                for (int k = 0; k < 3; k++) {
                    int q = tid + k * 256, m = q >> 5, col = (q & 31) * 8;
                    size_t so = ((size_t)m * HCD + (col >> 6) * NH + h0 + hb1 + (col & 63)) * 2;
                    unsigned dst = (st ^ 1) * FNH_STAGE + m * 528 + col * 2;
                    __pipeline_memcpy_async(smc + FNH_OFF + dst, (const char*)g_fnhi2 + so, 16);
                    __pipeline_memcpy_async(smc + FNL_OFF + dst, (const char*)g_fnlo2 + so, 16);
                }
                __pipeline_commit();
            }

            // ---- GEMM via HMMA: warp w handles k-chunks {w, w+8} (16 k each)
            #pragma unroll
            for (int cc = 0; cc < 2; cc++) {
                const int c = w + cc * 8;
                unsigned ah[4], al[4];
                ldsm_x4(smu + OUTH_OFF + st * OUT_STAGE + aRow + c * 32,
                        ah[0], ah[1], ah[2], ah[3]);
                ldsm_x4(smu + OUTL_OFF + st * OUT_STAGE + aRow + c * 32,
                        al[0], al[1], al[2], al[3]);
                #pragma unroll
                for (int j = 0; j < 3; j++) {
                    unsigned bh0, bh1, bl0, bl1;
                    const unsigned bo = st * FNH_STAGE + j * 8 * 528 + bRow + c * 32;
                    ldsm_x2(smu + FNH_OFF + bo, bh0, bh1);
                    ldsm_x2(smu + FNL_OFF + bo, bl0, bl1);
                    mma_bf16(D[j], ah, bh0, bh1);
                    mma_bf16(D[j], ah, bl0, bl1);
                    mma_bf16(D[j], al, bh0, bh1);
                }
            }
        }

        // --- logits reduction across 8 warps via red overlay
        __syncthreads();   // all GEMM reads of out/fn stages done
        {
            const int row = lane >> 2, col2 = (lane & 3) * 2;
            #pragma unroll
            for (int j = 0; j < 3; j++) {
                const int m = j * 8 + col2;
                red[((row)     * 24 + m)     * 8 + w] = D[j][0];
                red[((row)     * 24 + m + 1) * 8 + w] = D[j][1];
                red[((row + 8) * 24 + m)     * 8 + w] = D[j][2];
                red[((row + 8) * 24 + m + 1) * 8 + w] = D[j][3];
            }
        }
        __syncthreads();
        for (int o = tid; o < 384; o += 256) {
            const int row = o / 24, m = o % 24;
            float v = 0.f;
            #pragma unroll
            for (int ww = 0; ww < 8; ww++) v += red[(row * 24 + m) * 8 + ww];
            g_lp[by][b0 + row][m] = v;
        }

        // --- sumsq: 16 lanes share crow
        float v = ssq;
        v += __shfl_xor_sync(0xffffffffu, v, 1);
        v += __shfl_xor_sync(0xffffffffu, v, 2);
        v += __shfl_xor_sync(0xffffffffu, v, 4);
        v += __shfl_xor_sync(0xffffffffu, v, 8);
        if ((tid & 15) == 0) g_ssq[by][bg] = v;

        __syncthreads();   // red reads done before next tile's prologue reuses smem
    }
}

// ---------------------------------------------------------------------------
// Pass 2: per-row finalize — rms, softmax, sigmoid, Sinkhorn. One thread / row.
// ---------------------------------------------------------------------------
__global__ __launch_bounds__(256) void k_mid(
    const float* __restrict__ base, const float* __restrict__ scale,
    float* __restrict__ out)
{
    const int b = blockIdx.x * 256 + threadIdx.x;
    if (b >= NB) return;

    float lg[MIX];
    #pragma unroll
    for (int m = 0; m < MIX; m++)
        lg[m] = g_lp[0][b][m] + g_lp[1][b][m] + g_lp[2][b][m] + g_lp[3][b][m];
    const float ss = g_ssq[0][b] + g_ssq[1][b] + g_ssq[2][b] + g_ssq[3][b];
    const float inv = rsqrtf(ss * (1.0f / HCD) + 1e-6f);

    const float s0 = scale[0], s1 = scale[1], s2 = scale[2];

    float pre[4], mx = -1e30f;
    #pragma unroll
    for (int i = 0; i < 4; i++) {
        pre[i] = lg[i] * inv * s0 + base[i];
        mx = fmaxf(mx, pre[i]);
    }
    float e[4], den = 0.f;
    #pragma unroll
    for (int i = 0; i < 4; i++) { e[i] = expf(pre[i] - mx); den += e[i]; }
    const float rden = 1.f / den;
    #pragma unroll
    for (int i = 0; i < 4; i++) g_hpre[b][i] = e[i] * rden;

    #pragma unroll
    for (int i = 0; i < 4; i++) {
        const float p = lg[4 + i] * inv * s1 + base[4 + i];
        out[POST_OFF + (size_t)b * 4 + i] = 1.f / (1.f + expf(-p));
    }

    float M[4][4];
    #pragma unroll
    for (int i = 0; i < 4; i++)
        #pragma unroll
        for (int j = 0; j < 4; j++)
            M[i][j] = expf(lg[8 + i * 4 + j] * inv * s2 + base[8 + i * 4 + j]);
    #pragma unroll
    for (int it = 0; it < 10; it++) {
        #pragma unroll
        for (int i = 0; i < 4; i++) {
            const float r = 1.f / (M[i][0] + M[i][1] + M[i][2] + M[i][3] + 1e-6f);
            #pragma unroll
            for (int j = 0; j < 4; j++) M[i][j] *= r;
        }
        #pragma unroll
        for (int j = 0; j < 4; j++) {
            const float c = 1.f / (M[0][j] + M[1][j] + M[2][j] + M[3][j] + 1e-6f);
            #pragma unroll
            for (int i = 0; i < 4; i++) M[i][j] *= c;
        }
    }
    #pragma unroll
    for (int i = 0; i < 4; i++)
        #pragma unroll
        for (int j = 0; j < 4; j++)
            out[COMB_OFF + (size_t)b * 16 + i * 4 + j] = M[i][j];
}

// ---------------------------------------------------------------------------
// Pass 3: layer_input[b,h] = sum_n h_pre[b,n] * residual_cur[b,n,h]
// ---------------------------------------------------------------------------
__global__ __launch_bounds__(256) void k_layer(float* __restrict__ out)
{
    const int b = blockIdx.x;
    const int h = (blockIdx.y * 256 + threadIdx.x) << 2;
    const float h0 = g_hpre[b][0], h1 = g_hpre[b][1];
    const float h2 = g_hpre[b][2], h3 = g_hpre[b][3];
    const float* rp = out + RES_OFF + (size_t)b * 4 * NH;
    const float4 a0 = __ldcs((const float4*)(rp + h));
    const float4 a1 = __ldcs((const float4*)(rp + NH + h));
    const float4 a2 = __ldcs((const float4*)(rp + 2 * NH + h));
    const float4 a3 = __ldcs((const float4*)(rp + 3 * NH + h));
    float4 o;
    o.x = h0 * a0.x + h1 * a1.x + h2 * a2.x + h3 * a3.x;
    o.y = h0 * a0.y + h1 * a1.y + h2 * a2.y + h3 * a3.y;
    o.z = h0 * a0.z + h1 * a1.z + h2 * a2.z + h3 * a3.z;
    o.w = h0 * a0.w + h1 * a1.w + h2 * a2.w + h3 * a3.w;
    __stcs((float4*)(out + LAYER_OFF + (size_t)b * NH + h), o);
}

extern "C" void kernel_launch(void* const* d_in, const int* in_sizes, int n_in,
                              void* d_out, int out_size)
{
    const float* x     = (const float*)d_in[0];
    const float* rprev = (const float*)d_in[1];
    const float* postp = (const float*)d_in[2];
    const float* combp = (const float*)d_in[3];
    const float* fn    = (const float*)d_in[4];
    const float* base  = (const float*)d_in[5];
    const float* scale = (const float*)d_in[6];
    float* out = (float*)d_out;

    cudaFuncSetAttribute(k_pass1, cudaFuncAttributeMaxDynamicSharedMemorySize, SMEM_DYN);
    k_split_fn<<<24 * 16384 / 1024, 256>>>(fn);
    k_pass1<<<NBLK, 256, SMEM_DYN>>>(x, rprev, postp, combp, out);
    k_mid<<<NB / 256, 256>>>(base, scale, out);
    k_layer<<<dim3(NB, NH / 1024), 256>>>(out);
}

// round 13
// speedup vs baseline: 1.0623x; 1.0202x over previous
#include <cuda_runtime.h>
#include <cuda_pipeline.h>
#include <cuda_bf16.h>

// Problem constants
#define NB   4096
#define NH   4096
#define HCD  16384
#define MIX  24

// Pass-1 tiling
#define BM     16     // batch rows per block (= MMA M)
#define CH     64     // h per slab
#define HR     1024   // h range per block
#define NSLAB  16     // HR / CH

// d_out layout: residual_cur | post_mix | comb_mix | layer_input
#define RES_OFF   0ULL
#define POST_OFF  67108864ULL
#define COMB_OFF  (POST_OFF + 16384ULL)
#define LAYER_OFF (COMB_OFF + 65536ULL)

// dynamic smem (bytes): fnH[2][24][264] | fnL | outH[2][16][264] | outL   (bf16)
#define FNH_STAGE  12672              // 24*264*2
#define OUT_STAGE  8448               // 16*264*2
#define FNH_OFF    0
#define FNL_OFF    25344
#define OUTH_OFF   50688
#define OUTL_OFF   67584
#define SMEM_DYN   84480

typedef unsigned long long u64;

// Scratch (no allocations allowed -> __device__ globals)
__device__ unsigned g_fnhi2[24 * 16384 / 2];   // bf16x2-packed fn hi
__device__ unsigned g_fnlo2[24 * 16384 / 2];   // bf16x2-packed fn lo
__device__ float g_lp[4][NB][MIX];
__device__ float g_ssq[4][NB];
__device__ float g_hpre[NB][4];

__device__ __forceinline__ unsigned bf2pack(float e0, float e1) {
    __nv_bfloat162 v = __floats2bfloat162_rn(e0, e1);  // .x=e0 (lower), .y=e1
    unsigned r; memcpy(&r, &v, 4); return r;
}
__device__ __forceinline__ float bf_lo_f(unsigned u) { return __uint_as_float(u << 16); }
__device__ __forceinline__ float bf_hi_f(unsigned u) { return __uint_as_float(u & 0xffff0000u); }

__device__ __forceinline__ void ldsm_x4(unsigned addr, unsigned& r0, unsigned& r1,
                                        unsigned& r2, unsigned& r3) {
    asm volatile("ldmatrix.sync.aligned.m8n8.x4.shared.b16 {%0,%1,%2,%3}, [%4];"
                 : "=r"(r0), "=r"(r1), "=r"(r2), "=r"(r3) : "r"(addr));
}
__device__ __forceinline__ void ldsm_x2(unsigned addr, unsigned& r0, unsigned& r1) {
    asm volatile("ldmatrix.sync.aligned.m8n8.x2.shared.b16 {%0,%1}, [%2];"
                 : "=r"(r0), "=r"(r1) : "r"(addr));
}
__device__ __forceinline__ void mma_bf16(float* d, const unsigned* a, unsigned b0, unsigned b1) {
    asm volatile(
        "mma.sync.aligned.m16n8k16.row.col.f32.bf16.bf16.f32 "
        "{%0,%1,%2,%3}, {%4,%5,%6,%7}, {%8,%9}, {%0,%1,%2,%3};"
        : "+f"(d[0]), "+f"(d[1]), "+f"(d[2]), "+f"(d[3])
        : "r"(a[0]), "r"(a[1]), "r"(a[2]), "r"(a[3]), "r"(b0), "r"(b1));
}

// ---------------------------------------------------------------------------
// Pre-pass: split fn (fp32) into bf16 hi/lo device arrays. 24*16384 elements.
// ---------------------------------------------------------------------------
__global__ __launch_bounds__(256) void k_split_fn(const float* __restrict__ fn)
{
    const int t = blockIdx.x * 256 + threadIdx.x;     // 98304 threads, 4 el each
    const float4 v = *(const float4*)(fn + (size_t)t * 4);
    unsigned h01 = bf2pack(v.x, v.y), h23 = bf2pack(v.z, v.w);
    unsigned l01 = bf2pack(v.x - bf_lo_f(h01), v.y - bf_hi_f(h01));
    unsigned l23 = bf2pack(v.z - bf_lo_f(h23), v.w - bf_hi_f(h23));
    g_fnhi2[t * 2] = h01; g_fnhi2[t * 2 + 1] = h23;
    g_fnlo2[t * 2] = l01; g_fnlo2[t * 2 + 1] = l23;
}

// ---------------------------------------------------------------------------
// Pass 1: residual_cur = comb@residual_prev + post*x ; write it; fused sumsq
// and 24 raw dots vs fn — dots via bf16 split-precision HMMA (m16n8k16).
// Residual writes use DEFAULT cache policy: the tail-written stripes stay in
// L2 for k_layer's producer->consumer reuse (read back in reverse order).
// Grid: (NB/BM, NH/HR) = (256, 4), 256 threads (8 warps), 2 blocks/SM.
// ---------------------------------------------------------------------------
__global__ __launch_bounds__(256, 2) void k_pass1(
    const float* __restrict__ x, const float* __restrict__ rprev,
    const float* __restrict__ postp, const float* __restrict__ combp,
    float* __restrict__ out)
{
    extern __shared__ char smc[];
    float* red = (float*)(smc + OUTH_OFF);   // overlay [384][8], epilogue only
    const unsigned smu = (unsigned)__cvta_generic_to_shared(smc);

    __shared__ float comb_s[BM][16];
    __shared__ float post_s[BM][4];

    const int tid  = threadIdx.x;
    const int lane = tid & 31;
    const int w    = tid >> 5;               // warp 0..7
    const int b0   = blockIdx.x * BM;
    const int h0   = blockIdx.y * HR;

    for (int i = tid; i < BM * 16; i += 256)
        comb_s[i >> 4][i & 15] = combp[(size_t)(b0 + (i >> 4)) * 16 + (i & 15)];
    if (tid < BM * 4)
        post_s[tid >> 2][tid & 3] = postp[(size_t)b0 * 4 + tid];

    // compute-phase mapping: one float4-of-h per thread, fixed row
    const int crow = tid >> 4;               // 0..15
    const int ch4  = (tid & 15) << 2;        // 0..60

    const int bg = b0 + crow;
    const float* xrow = x + (size_t)bg * NH;
    const float* rrow = rprev + (size_t)bg * 4 * NH;
    float* orow = out + RES_OFF + (size_t)bg * 4 * NH;

    // prologue: cp.async fn slab 0 (stage 0)
    {
        #pragma unroll
        for (int k = 0; k < 3; k++) {
            int q = tid + k * 256, m = q >> 5, col = (q & 31) * 8;
            size_t so = ((size_t)m * HCD + (col >> 6) * NH + h0 + (col & 63)) * 2;
            unsigned dst = m * 528 + col * 2;
            __pipeline_memcpy_async(smc + FNH_OFF + dst, (const char*)g_fnhi2 + so, 16);
            __pipeline_memcpy_async(smc + FNL_OFF + dst, (const char*)g_fnlo2 + so, 16);
        }
        __pipeline_commit();
    }

    float4 xv_p = __ldcs((const float4*)(xrow + h0 + ch4));
    float4 rv_p[4];
    #pragma unroll
    for (int j = 0; j < 4; j++)
        rv_p[j] = __ldcs((const float4*)(rrow + (size_t)j * NH + h0 + ch4));

    float D[3][4];
    #pragma unroll
    for (int j = 0; j < 3; j++)
        #pragma unroll
        for (int r = 0; r < 4; r++) D[j][r] = 0.f;
    float ssq = 0.f;

    // ldmatrix lane address components (byte offsets within a stage)
    const unsigned aRow = (lane & 15) * 528 + ((lane >> 4) << 4);      // + c*32
    const unsigned bRow = (lane & 7) * 528 + (((lane >> 3) & 1) << 4); // + j*8*528 + c*32

    __syncthreads();   // comb_s/post_s visible

    for (int s = 0; s < NSLAB; s++) {
        const int st = s & 1;
        const int hh0 = h0 + s * CH;

        // ---- A phase: residual compute; fp32 to gmem; bf16 hi/lo to smem
        {
            const int hg = hh0 + ch4;
            const unsigned ob = st * OUT_STAGE + crow * 528 + ch4 * 2; // +n*128
            #pragma unroll
            for (int n = 0; n < 4; n++) {
                const float ppn = post_s[crow][n];
                float4 o;
                o.x = ppn * xv_p.x; o.y = ppn * xv_p.y;
                o.z = ppn * xv_p.z; o.w = ppn * xv_p.w;
                #pragma unroll
                for (int j = 0; j < 4; j++) {
                    const float cbv = comb_s[crow][n * 4 + j];
                    o.x += cbv * rv_p[j].x; o.y += cbv * rv_p[j].y;
                    o.z += cbv * rv_p[j].z; o.w += cbv * rv_p[j].w;
                }
                *(float4*)(orow + (size_t)n * NH + hg) = o;   // default policy: keep in L2
                ssq += o.x * o.x + o.y * o.y + o.z * o.z + o.w * o.w;

                unsigned h01 = bf2pack(o.x, o.y), h23 = bf2pack(o.z, o.w);
                unsigned l01 = bf2pack(o.x - bf_lo_f(h01), o.y - bf_hi_f(h01));
                unsigned l23 = bf2pack(o.z - bf_lo_f(h23), o.w - bf_hi_f(h23));
                *(u64*)(smc + OUTH_OFF + ob + n * 128) = (u64)h01 | ((u64)h23 << 32);
                *(u64*)(smc + OUTL_OFF + ob + n * 128) = (u64)l01 | ((u64)l23 << 32);
            }
        }

        // distance-1 register prefetch of raw operands for slab s+1
        if (s + 1 < NSLAB) {
            const int hg1 = hh0 + CH + ch4;
            xv_p = __ldcs((const float4*)(xrow + hg1));
            #pragma unroll
            for (int j = 0; j < 4; j++)
                rv_p[j] = __ldcs((const float4*)(rrow + (size_t)j * NH + hg1));
        }

        __pipeline_wait_prior(0);
        __syncthreads();   // fn(s)+out(s) visible; GEMM(s-1) done everywhere

        // prefetch fn slab s+1 into the other stage
        if (s + 1 < NSLAB) {
            const int hb1 = (s + 1) * CH;
            #pragma unroll
            for (int k = 0; k < 3; k++) {
                int q = tid + k * 256, m = q >> 5, col = (q & 31) * 8;
                size_t so = ((size_t)m * HCD + (col >> 6) * NH + h0 + hb1 + (col & 63)) * 2;
                unsigned dst = (st ^ 1) * FNH_STAGE + m * 528 + col * 2;
                __pipeline_memcpy_async(smc + FNH_OFF + dst, (const char*)g_fnhi2 + so, 16);
                __pipeline_memcpy_async(smc + FNL_OFF + dst, (const char*)g_fnlo2 + so, 16);
            }
            __pipeline_commit();
        }

        // ---- GEMM via HMMA: warp w handles k-chunks {w, w+8} (16 k each)
        #pragma unroll
        for (int cc = 0; cc < 2; cc++) {
            const int c = w + cc * 8;
            unsigned ah[4], al[4];
            ldsm_x4(smu + OUTH_OFF + st * OUT_STAGE + aRow + c * 32,
                    ah[0], ah[1], ah[2], ah[3]);
            ldsm_x4(smu + OUTL_OFF + st * OUT_STAGE + aRow + c * 32,
                    al[0], al[1], al[2], al[3]);
            #pragma unroll
            for (int j = 0; j < 3; j++) {
                unsigned bh0, bh1, bl0, bl1;
                const unsigned bo = st * FNH_STAGE + j * 8 * 528 + bRow + c * 32;
                ldsm_x2(smu + FNH_OFF + bo, bh0, bh1);
                ldsm_x2(smu + FNL_OFF + bo, bl0, bl1);
                mma_bf16(D[j], ah, bh0, bh1);
                mma_bf16(D[j], ah, bl0, bl1);
                mma_bf16(D[j], al, bh0, bh1);
            }
        }
    }

    // --- logits reduction across 8 warps via red overlay
    __syncthreads();   // all GEMM reads of out/fn stages done
    {
        const int row = lane >> 2, col2 = (lane & 3) * 2;
        #pragma unroll
        for (int j = 0; j < 3; j++) {
            const int m = j * 8 + col2;
            red[((row)     * 24 + m)     * 8 + w] = D[j][0];
            red[((row)     * 24 + m + 1) * 8 + w] = D[j][1];
            red[((row + 8) * 24 + m)     * 8 + w] = D[j][2];
            red[((row + 8) * 24 + m + 1) * 8 + w] = D[j][3];
        }
    }
    __syncthreads();
    for (int o = tid; o < 384; o += 256) {
        const int row = o / 24, m = o % 24;
        float v = 0.f;
        #pragma unroll
        for (int ww = 0; ww < 8; ww++) v += red[(row * 24 + m) * 8 + ww];
        g_lp[blockIdx.y][b0 + row][m] = v;
    }

    // --- sumsq: 16 lanes share crow
    float v = ssq;
    v += __shfl_xor_sync(0xffffffffu, v, 1);
    v += __shfl_xor_sync(0xffffffffu, v, 2);
    v += __shfl_xor_sync(0xffffffffu, v, 4);
    v += __shfl_xor_sync(0xffffffffu, v, 8);
    if ((tid & 15) == 0) g_ssq[blockIdx.y][bg] = v;
}

// ---------------------------------------------------------------------------
// Pass 2: per-row finalize — rms, softmax, sigmoid, Sinkhorn. One thread / row.
// ---------------------------------------------------------------------------
__global__ __launch_bounds__(256) void k_mid(
    const float* __restrict__ base, const float* __restrict__ scale,
    float* __restrict__ out)
{
    const int b = blockIdx.x * 256 + threadIdx.x;
    if (b >= NB) return;

    float lg[MIX];
    #pragma unroll
    for (int m = 0; m < MIX; m++)
        lg[m] = g_lp[0][b][m] + g_lp[1][b][m] + g_lp[2][b][m] + g_lp[3][b][m];
    const float ss = g_ssq[0][b] + g_ssq[1][b] + g_ssq[2][b] + g_ssq[3][b];
    const float inv = rsqrtf(ss * (1.0f / HCD) + 1e-6f);

    const float s0 = scale[0], s1 = scale[1], s2 = scale[2];

    float pre[4], mx = -1e30f;
    #pragma unroll
    for (int i = 0; i < 4; i++) {
        pre[i] = lg[i] * inv * s0 + base[i];
        mx = fmaxf(mx, pre[i]);
    }
    float e[4], den = 0.f;
    #pragma unroll
    for (int i = 0; i < 4; i++) { e[i] = expf(pre[i] - mx); den += e[i]; }
    const float rden = 1.f / den;
    #pragma unroll
    for (int i = 0; i < 4; i++) g_hpre[b][i] = e[i] * rden;

    #pragma unroll
    for (int i = 0; i < 4; i++) {
        const float p = lg[4 + i] * inv * s1 + base[4 + i];
        out[POST_OFF + (size_t)b * 4 + i] = 1.f / (1.f + expf(-p));
    }

    float M[4][4];
    #pragma unroll
    for (int i = 0; i < 4; i++)
        #pragma unroll
        for (int j = 0; j < 4; j++)
            M[i][j] = expf(lg[8 + i * 4 + j] * inv * s2 + base[8 + i * 4 + j]);
    #pragma unroll
    for (int it = 0; it < 10; it++) {
        #pragma unroll
        for (int i = 0; i < 4; i++) {
            const float r = 1.f / (M[i][0] + M[i][1] + M[i][2] + M[i][3] + 1e-6f);
            #pragma unroll
            for (int j = 0; j < 4; j++) M[i][j] *= r;
        }
        #pragma unroll
        for (int j = 0; j < 4; j++) {
            const float c = 1.f / (M[0][j] + M[1][j] + M[2][j] + M[3][j] + 1e-6f);
            #pragma unroll
            for (int i = 0; i < 4; i++) M[i][j] *= c;
        }
    }
    #pragma unroll
    for (int i = 0; i < 4; i++)
        #pragma unroll
        for (int j = 0; j < 4; j++)
            out[COMB_OFF + (size_t)b * 16 + i * 4 + j] = M[i][j];
}

// ---------------------------------------------------------------------------
// Pass 3: layer_input[b,h] = sum_n h_pre[b,n] * residual_cur[b,n,h]
// Reads residual_cur in REVERSE h-stripe order (LIFO vs pass1's write order)
// with default cache policy -> tail stripes hit in L2.
// ---------------------------------------------------------------------------
__global__ __launch_bounds__(256) void k_layer(float* __restrict__ out)
{
    const int b = blockIdx.x;
    const int hq = 3 - blockIdx.y;            // consume stripes newest-first
    const int h = hq * 1024 + (threadIdx.x << 2);
    const float h0 = g_hpre[b][0], h1 = g_hpre[b][1];
    const float h2 = g_hpre[b][2], h3 = g_hpre[b][3];
    const float* rp = out + RES_OFF + (size_t)b * 4 * NH;
    const float4 a0 = *(const float4*)(rp + h);
    const float4 a1 = *(const float4*)(rp + NH + h);
    const float4 a2 = *(const float4*)(rp + 2 * NH + h);
    const float4 a3 = *(const float4*)(rp + 3 * NH + h);
    float4 o;
    o.x = h0 * a0.x + h1 * a1.x + h2 * a2.x + h3 * a3.x;
    o.y = h0 * a0.y + h1 * a1.y + h2 * a2.y + h3 * a3.y;
    o.z = h0 * a0.z + h1 * a1.z + h2 * a2.z + h3 * a3.z;
    o.w = h0 * a0.w + h1 * a1.w + h2 * a2.w + h3 * a3.w;
    __stcs((float4*)(out + LAYER_OFF + (size_t)b * NH + h), o);
}

extern "C" void kernel_launch(void* const* d_in, const int* in_sizes, int n_in,
                              void* d_out, int out_size)
{
    const float* x     = (const float*)d_in[0];
    const float* rprev = (const float*)d_in[1];
    const float* postp = (const float*)d_in[2];
    const float* combp = (const float*)d_in[3];
    const float* fn    = (const float*)d_in[4];
    const float* base  = (const float*)d_in[5];
    const float* scale = (const float*)d_in[6];
    float* out = (float*)d_out;

    cudaFuncSetAttribute(k_pass1, cudaFuncAttributeMaxDynamicSharedMemorySize, SMEM_DYN);
    k_split_fn<<<24 * 16384 / 1024, 256>>>(fn);
    k_pass1<<<dim3(NB / BM, NH / HR), 256, SMEM_DYN>>>(x, rprev, postp, combp, out);
    k_mid<<<NB / 256, 256>>>(base, scale, out);
    k_layer<<<dim3(NB, NH / 1024), 256>>>(out);
}